// round 15
// baseline (speedup 1.0000x reference)
#include <cuda_runtime.h>
#include <math.h>

// ---------------- Problem constants ----------------
#define NQ    8
#define DDIM  1024
#define CD    32
#define KC    1024
#define BB    16
#define TT    4096
#define TILE  32
#define NTHR  768
#define NWARP 24
#define NCTA  148
#define NTILES ((BB*TT)/TILE)                // 2048 tiles
#define QOFF  ((size_t)BB*DDIM*TT)
#define IOFF  (QOFF + (size_t)NQ*BB*TT)
#define RTP   1028                            // R_T row pitch (floats)

// Shared memory layout (floats)
#define SM_RT    0                            // R transposed [32][1028] = 32896
#define SM_W     32896                        // two 32x256 buffers = 16384
#define SM_ZE    (SM_W + 2*CD*256)            // 49280  ZE[c*33+t]
#define SM_ENCT  (SM_ZE + CD*33)              // 50336  ENC transposed [t][36]
#define SM_ZQST  (SM_ENCT + 32*36)            // 51488  STE z_q transposed [t][36]
#define SM_BV    (SM_ZQST + 32*36)            // 52640  32 batches x 32 t
#define SM_BI    (SM_BV + 1024)               // 53664
#define SM_FLOATS (SM_BI + 1024)              // 54688
#define SMEM_BYTES (SM_FLOATS * 4)            // 218752 bytes

__device__ float g_cbn_v11[NQ*KC*CD];
__device__ float g_losspart_v11[NQ*NTILES];
__device__ int   g_tick_v11;

__device__ __forceinline__ void grid_barrier(int tid) {
    __syncthreads();
    if (tid == 0) {
        __threadfence();
        int t = atomicAdd(&g_tick_v11, 1);
        int target = (t / NCTA + 1) * NCTA;
        while (*(volatile int*)&g_tick_v11 < target) { }
        __threadfence();
    }
    __syncthreads();
}

__device__ __forceinline__ unsigned f2ord(float f) {
    int b = __float_as_int(f);
    return (b >= 0) ? ((unsigned)b | 0x80000000u) : ~(unsigned)b;
}

__device__ __forceinline__ void cp_async16(unsigned s, const void* g) {
    asm volatile("cp.async.cg.shared.global [%0], [%1], 16;" :: "r"(s), "l"(g));
}
#define CP_COMMIT() asm volatile("cp.async.commit_group;")
#define CP_WAIT0()  asm volatile("cp.async.wait_group 0;")

// 32-term ascending-c fma chain (bitwise = v8/v9/v10)
#define SIM_CHAIN(sv, A0,A1,A2,A3,A4,A5,A6,A7, E0,E1,E2,E3,E4,E5,E6,E7) \
    sv = 0.f; \
    sv = fmaf(A0.x,E0.x,sv); sv = fmaf(A0.y,E0.y,sv); \
    sv = fmaf(A0.z,E0.z,sv); sv = fmaf(A0.w,E0.w,sv); \
    sv = fmaf(A1.x,E1.x,sv); sv = fmaf(A1.y,E1.y,sv); \
    sv = fmaf(A1.z,E1.z,sv); sv = fmaf(A1.w,E1.w,sv); \
    sv = fmaf(A2.x,E2.x,sv); sv = fmaf(A2.y,E2.y,sv); \
    sv = fmaf(A2.z,E2.z,sv); sv = fmaf(A2.w,E2.w,sv); \
    sv = fmaf(A3.x,E3.x,sv); sv = fmaf(A3.y,E3.y,sv); \
    sv = fmaf(A3.z,E3.z,sv); sv = fmaf(A3.w,E3.w,sv); \
    sv = fmaf(A4.x,E4.x,sv); sv = fmaf(A4.y,E4.y,sv); \
    sv = fmaf(A4.z,E4.z,sv); sv = fmaf(A4.w,E4.w,sv); \
    sv = fmaf(A5.x,E5.x,sv); sv = fmaf(A5.y,E5.y,sv); \
    sv = fmaf(A5.z,E5.z,sv); sv = fmaf(A5.w,E5.w,sv); \
    sv = fmaf(A6.x,E6.x,sv); sv = fmaf(A6.y,E6.y,sv); \
    sv = fmaf(A6.z,E6.z,sv); sv = fmaf(A6.w,E6.w,sv); \
    sv = fmaf(A7.x,E7.x,sv); sv = fmaf(A7.y,E7.y,sv); \
    sv = fmaf(A7.z,E7.z,sv); sv = fmaf(A7.w,E7.w,sv);

// ---------------- Single persistent kernel ----------------
__global__ __launch_bounds__(NTHR, 1)
void rvq_persist_v11(const float* __restrict__ x,
                     const float* __restrict__ in_w,
                     const float* __restrict__ in_b,
                     const float* __restrict__ out_w,
                     const float* __restrict__ out_b,
                     const float* __restrict__ cb,
                     float* __restrict__ out)
{
    extern __shared__ float sm[];
    float* RT   = sm + SM_RT;
    float* W0   = sm + SM_W;
    float* W1   = sm + SM_W + CD*256;
    float* ZE   = sm + SM_ZE;
    float* ENCT = sm + SM_ENCT;
    float* ZQST = sm + SM_ZQST;
    float* BV   = sm + SM_BV;
    int*   BI   = (int*)(sm + SM_BI);

    const int tid  = threadIdx.x;
    const int lane = tid & 31;
    const int wg   = tid >> 5;               // 0..23
    const int bid  = blockIdx.x;

    // ===== Prologue: normalize codebook rows (jnp rounding mimicry) =====
    {
        int gid = bid * NTHR + tid;
        if (gid < NQ*KC) {
            const float* src = cb + (size_t)gid * CD;
            float v[CD];
            float ss = 0.f;
#pragma unroll
            for (int c = 0; c < CD; c++) {
                v[c] = src[c];
                float vv = v[c] * v[c];
                ss = ss + vv;
            }
            float n = fmaxf(sqrtf(ss), 1e-12f);
            float* dst = g_cbn_v11 + (size_t)gid * CD;
#pragma unroll
            for (int c = 0; c < CD; c++) dst[c] = v[c] / n;
            __threadfence();
        }
    }
    grid_barrier(tid);

    // ===== Tile loop =====
    for (int blk = bid; blk < NTILES; blk += NCTA) {
        const int b  = blk >> 7;
        const int t0 = (blk & 127) << 5;
        const float* xg = x + (size_t)b * DDIM * TT + t0;

        // load residual tile transposed: RT[t][d]
        for (int i = tid; i < DDIM*TILE; i += NTHR) {
            int d = i >> 5, t = i & 31;
            RT[t*RTP + d] = xg[(size_t)d * TT + t];
        }
        __syncthreads();

        for (int q = 0; q < NQ; q++) {
            const float* inw_q = in_w + (size_t)q * CD * DDIM;

            // pre-stage W chunk 0 via cp.async (all threads)
            {
                unsigned wb = (unsigned)__cvta_generic_to_shared(W0);
                for (int j = tid; j < CD*64; j += NTHR) {
                    int c = j >> 6, dq = j & 63;
                    cp_async16(wb + j*16, inw_q + (size_t)c*DDIM + dq*4);
                }
                CP_COMMIT();
            }

            // ===== Phase A: z_e = in_w @ R (8 warps x 4 ch; v5/v7/v10-bitwise) =====
            const int c0 = (wg & 7) * 4;
            float acc0 = 0.f, acc1 = 0.f, acc2 = 0.f, acc3 = 0.f;

            for (int ci = 0; ci < 4; ci++) {
                CP_WAIT0();
                __syncthreads();     // chunk ci visible
                if (ci < 3) {        // stage next chunk (all threads), overlapped
                    float* Wn = ((ci+1) & 1) ? W1 : W0;
                    unsigned wb = (unsigned)__cvta_generic_to_shared(Wn);
                    const int dcn = (ci+1) * 256;
                    for (int j = tid; j < CD*64; j += NTHR) {
                        int c = j >> 6, dq = j & 63;
                        cp_async16(wb + j*16, inw_q + (size_t)c*DDIM + dcn + dq*4);
                    }
                    CP_COMMIT();
                }
                if (wg < 8) {
                    const int dc = ci * 256;
                    const float* Wb  = (ci & 1) ? W1 : W0;
                    const float* Wr0 = Wb + (c0+0)*256;
                    const float* Wr1 = Wb + (c0+1)*256;
                    const float* Wr2 = Wb + (c0+2)*256;
                    const float* Wr3 = Wb + (c0+3)*256;
                    const float* Rrow = RT + lane*RTP + dc;
#pragma unroll 4
                    for (int dd = 0; dd < 256; dd += 4) {
                        float4 rv = *(const float4*)(Rrow + dd);
                        float4 w0 = *(const float4*)(Wr0 + dd);
                        float4 w1 = *(const float4*)(Wr1 + dd);
                        float4 w2 = *(const float4*)(Wr2 + dd);
                        float4 w3 = *(const float4*)(Wr3 + dd);
                        // strict ascending d within group (bitwise = v5/v7/v10)
                        acc0 = fmaf(w0.x, rv.x, acc0); acc0 = fmaf(w0.y, rv.y, acc0);
                        acc0 = fmaf(w0.z, rv.z, acc0); acc0 = fmaf(w0.w, rv.w, acc0);
                        acc1 = fmaf(w1.x, rv.x, acc1); acc1 = fmaf(w1.y, rv.y, acc1);
                        acc1 = fmaf(w1.z, rv.z, acc1); acc1 = fmaf(w1.w, rv.w, acc1);
                        acc2 = fmaf(w2.x, rv.x, acc2); acc2 = fmaf(w2.y, rv.y, acc2);
                        acc2 = fmaf(w2.z, rv.z, acc2); acc2 = fmaf(w2.w, rv.w, acc2);
                        acc3 = fmaf(w3.x, rv.x, acc3); acc3 = fmaf(w3.y, rv.y, acc3);
                        acc3 = fmaf(w3.z, rv.z, acc3); acc3 = fmaf(w3.w, rv.w, acc3);
                    }
                }
                if (ci < 3) __syncthreads();  // protect buffer reuse
            }
            if (wg < 8) {
                const float* inb_q = in_b + q*CD;    // bias AFTER contraction
                ZE[(c0+0)*33 + lane] = acc0 + __ldg(inb_q + c0 + 0);
                ZE[(c0+1)*33 + lane] = acc1 + __ldg(inb_q + c0 + 1);
                ZE[(c0+2)*33 + lane] = acc2 + __ldg(inb_q + c0 + 2);
                ZE[(c0+3)*33 + lane] = acc3 + __ldg(inb_q + c0 + 3);
            }
            __syncthreads();

            // prefetch pass-0 cbn row: batch wg covers codes [wg*32, wg*32+32)
            const float* cbn_q = g_cbn_v11 + (size_t)q * KC * CD;
            const float4* rp0 = (const float4*)(cbn_q + (size_t)(wg*32 + lane) * CD);
            float4 ra0 = __ldg(rp0+0), ra1 = __ldg(rp0+1), ra2 = __ldg(rp0+2), ra3 = __ldg(rp0+3);
            float4 ra4 = __ldg(rp0+4), ra5 = __ldg(rp0+5), ra6 = __ldg(rp0+6), ra7 = __ldg(rp0+7);

            // ===== enc (bitwise = v6/v9/v10), transposed store =====
            if (wg == 0) {
                float n2 = 0.f;
#pragma unroll
                for (int c = 0; c < CD; c++) {
                    float z = ZE[c*33 + lane];
                    float zz = z * z;
                    n2 = n2 + zz;
                }
                float n = fmaxf(sqrtf(n2), 1e-12f);
#pragma unroll
                for (int c = 0; c < CD; c++)
                    ENCT[lane*36 + c] = ZE[c*33 + lane] / n;
            }
            __syncthreads();

            // ===== Phase B pass 0: 24 warps, one batch each (semantics = v10) =====
            {
                float bestv = 0.f; int bestk = 0;
                for (int t = 0; t < TILE; t++) {
                    const float4* ev = (const float4*)(ENCT + t*36);
                    float4 e0 = ev[0], e1 = ev[1], e2 = ev[2], e3 = ev[3];
                    float4 e4 = ev[4], e5 = ev[5], e6 = ev[6], e7 = ev[7];
                    float s0;
                    SIM_CHAIN(s0, ra0,ra1,ra2,ra3,ra4,ra5,ra6,ra7, e0,e1,e2,e3,e4,e5,e6,e7);
                    unsigned u0 = f2ord(s0);
                    unsigned m0 = __reduce_max_sync(0xffffffffu, u0);
                    unsigned q0 = __ballot_sync(0xffffffffu, u0 == m0);
                    int l0 = __ffs(q0) - 1;                  // lowest lane = lowest k
                    float sb0 = __shfl_sync(0xffffffffu, s0, l0);
                    int   kb0 = wg*32 + l0;
                    if (lane == t) { bestv = sb0; bestk = kb0; }
                }
                BV[wg*32 + lane] = bestv;
                BI[wg*32 + lane] = bestk;
            }
            // ===== Phase B pass 1: warps 0..7 handle batches 24..31 =====
            if (wg < 8) {
                const int batch = 24 + wg;
                const float4* rp1 = (const float4*)(cbn_q + (size_t)(batch*32 + lane) * CD);
                float4 rb0 = __ldg(rp1+0), rb1 = __ldg(rp1+1), rb2 = __ldg(rp1+2), rb3 = __ldg(rp1+3);
                float4 rb4 = __ldg(rp1+4), rb5 = __ldg(rp1+5), rb6 = __ldg(rp1+6), rb7 = __ldg(rp1+7);
                float bestv = 0.f; int bestk = 0;
                for (int t = 0; t < TILE; t++) {
                    const float4* ev = (const float4*)(ENCT + t*36);
                    float4 e0 = ev[0], e1 = ev[1], e2 = ev[2], e3 = ev[3];
                    float4 e4 = ev[4], e5 = ev[5], e6 = ev[6], e7 = ev[7];
                    float s1;
                    SIM_CHAIN(s1, rb0,rb1,rb2,rb3,rb4,rb5,rb6,rb7, e0,e1,e2,e3,e4,e5,e6,e7);
                    unsigned u1 = f2ord(s1);
                    unsigned m1 = __reduce_max_sync(0xffffffffu, u1);
                    unsigned q1 = __ballot_sync(0xffffffffu, u1 == m1);
                    int l1 = __ffs(q1) - 1;
                    float sb1 = __shfl_sync(0xffffffffu, s1, l1);
                    int   kb1 = batch*32 + l1;
                    if (lane == t) { bestv = sb1; bestk = kb1; }
                }
                BV[batch*32 + lane] = bestv;
                BI[batch*32 + lane] = bestk;
            }
            __syncthreads();

            // cross-batch merge (ascending k ranges; strict > keeps lowest k)
            if (wg == 0) {
                float fb = BV[lane]; int fi = BI[lane];
#pragma unroll
                for (int bt = 1; bt < 32; bt++) {
                    float v = BV[bt*32 + lane];
                    if (v > fb) { fb = v; fi = BI[bt*32 + lane]; }
                }
                BI[lane] = fi;
                out[QOFF + ((size_t)q * BB + b) * TT + t0 + lane] = (float)fi;
            }
            __syncthreads();

            // prefetch pass-0 out_w row for Phase C (hidden behind loss section)
            const float* outw_q = out_w + (size_t)q * DDIM * CD;
            const float* outb_q = out_b + (size_t)q * DDIM;
            const int d0 = wg*32 + lane;             // rows 0..767
            const float4* wp0 = (const float4*)(outw_q + (size_t)d0 * CD);
            float4 wa0 = __ldg(wp0+0), wa1 = __ldg(wp0+1), wa2 = __ldg(wp0+2), wa3 = __ldg(wp0+3);
            float4 wa4 = __ldg(wp0+4), wa5 = __ldg(wp0+5), wa6 = __ldg(wp0+6), wa7 = __ldg(wp0+7);
            float ob0 = __ldg(outb_q + d0);

            // loss partial + STE build, z_q gathered directly from gmem
            {
                const float* cb_q = cb + (size_t)q * KC * CD;
                float lp = 0.f;
                for (int i = tid; i < CD*TILE; i += NTHR) {
                    int c = i >> 5, t = i & 31;
                    float ze = ZE[c*33 + t];
                    float zq = __ldg(cb_q + (size_t)BI[t] * CD + c);
                    float dv = ze - zq;
                    lp = fmaf(dv, dv, lp);
                    float dlt = zq - ze;          // STE: fl(z_e + fl(z_q - z_e))
                    ZQST[t*36 + c] = ze + dlt;
                }
#pragma unroll
                for (int o = 16; o; o >>= 1) lp += __shfl_down_sync(0xffffffffu, lp, o);
                if (lane == 0) BV[wg] = lp;
            }
            __syncthreads();
            if (tid == 0) {
                float s = 0.f;
#pragma unroll
                for (int w2 = 0; w2 < NWARP; w2++) s += BV[w2];
                g_losspart_v11[q*NTILES + blk] = s;
            }

            // ===== Phase C pass 0: 24 warps x 1 row (values = v8/v9/v10) =====
            {
                for (int t = 0; t < TILE; t++) {
                    const float4* zv = (const float4*)(ZQST + t*36);
                    float4 z0 = zv[0], z1 = zv[1], z2 = zv[2], z3 = zv[3];
                    float4 z4 = zv[4], z5 = zv[5], z6 = zv[6], z7 = zv[7];
                    float v0;
                    SIM_CHAIN(v0, wa0,wa1,wa2,wa3,wa4,wa5,wa6,wa7, z0,z1,z2,z3,z4,z5,z6,z7);
                    float o0 = v0 + ob0;          // bias after contraction
                    RT[t*RTP + d0] = RT[t*RTP + d0] - o0;
                }
            }
            // ===== Phase C pass 1: warps 0..7 handle rows 768..1023 =====
            if (wg < 8) {
                const int d1 = 768 + wg*32 + lane;
                const float4* wp1 = (const float4*)(outw_q + (size_t)d1 * CD);
                float4 wb0 = __ldg(wp1+0), wb1 = __ldg(wp1+1), wb2 = __ldg(wp1+2), wb3 = __ldg(wp1+3);
                float4 wb4 = __ldg(wp1+4), wb5 = __ldg(wp1+5), wb6 = __ldg(wp1+6), wb7 = __ldg(wp1+7);
                float ob1 = __ldg(outb_q + d1);
                for (int t = 0; t < TILE; t++) {
                    const float4* zv = (const float4*)(ZQST + t*36);
                    float4 z0 = zv[0], z1 = zv[1], z2 = zv[2], z3 = zv[3];
                    float4 z4 = zv[4], z5 = zv[5], z6 = zv[6], z7 = zv[7];
                    float v1;
                    SIM_CHAIN(v1, wb0,wb1,wb2,wb3,wb4,wb5,wb6,wb7, z0,z1,z2,z3,z4,z5,z6,z7);
                    float o1 = v1 + ob1;
                    RT[t*RTP + d1] = RT[t*RTP + d1] - o1;
                }
            }
            __syncthreads();
        }

        // quantized_out = x - residual_final
        float* qo = out + (size_t)b * DDIM * TT + t0;
        for (int i = tid; i < DDIM*TILE; i += NTHR) {
            int d = i >> 5, t = i & 31;
            qo[(size_t)d * TT + t] = xg[(size_t)d * TT + t] - RT[t*RTP + d];
        }
        __syncthreads();
    }

    // ===== Epilogue: deterministic loss reduction (CTAs 0..7) =====
    if (tid == 0) __threadfence();
    grid_barrier(tid);
    if (bid < NQ) {
        float* red = sm;
        int q = bid;
        float s = 0.f;
        for (int i = tid; i < NTILES; i += NTHR) s += g_losspart_v11[q*NTILES + i];
        red[tid] = s;
        if (tid < 256) red[NTHR + tid] = 0.f;   // pad 768 -> 1024
        __syncthreads();
        for (int o = 512; o; o >>= 1) {
            if (tid < o) red[tid] += red[tid + o];
            __syncthreads();
        }
        if (tid == 0)
            out[IOFF + q] = 1.25f * red[0] * (1.0f / (float)(BB*CD*TT));
    }
}

// ---------------- launch ----------------
extern "C" void kernel_launch(void* const* d_in, const int* in_sizes, int n_in,
                              void* d_out, int out_size) {
    const float* x     = (const float*)d_in[0];
    const float* in_w  = (const float*)d_in[1];
    const float* in_b  = (const float*)d_in[2];
    const float* out_w = (const float*)d_in[3];
    const float* out_b = (const float*)d_in[4];
    const float* cb    = (const float*)d_in[5];
    float* out = (float*)d_out;

    cudaFuncSetAttribute(rvq_persist_v11, cudaFuncAttributeMaxDynamicSharedMemorySize, SMEM_BYTES);
    rvq_persist_v11<<<NCTA, NTHR, SMEM_BYTES>>>(x, in_w, in_b, out_w, out_b, cb, out);
}

// round 17
// speedup vs baseline: 1.1992x; 1.1992x over previous
#include <cuda_runtime.h>
#include <math.h>

// ---------------- Problem constants ----------------
#define NQ    8
#define DDIM  1024
#define CD    32
#define KC    1024
#define BB    16
#define TT    4096
#define TILE  32
#define NTHR  512
#define NWARP 16
#define NCTA  148
#define NTILES ((BB*TT)/TILE)                // 2048 tiles
#define QOFF  ((size_t)BB*DDIM*TT)
#define IOFF  (QOFF + (size_t)NQ*BB*TT)
#define RTP   1028                            // R_T row pitch (floats)

// Shared memory layout (floats)  (identical to v10)
#define SM_RT    0                            // R transposed [32][1028] = 32896
#define SM_W     32896                        // two 32x256 buffers = 16384
#define SM_ZE    (SM_W + 2*CD*256)            // 49280  ZE[c*33+t]
#define SM_ENCT  (SM_ZE + CD*33)              // 50336  ENC transposed [t][36]
#define SM_ZQST  (SM_ENCT + 32*36)            // 51488  STE z_q transposed [t][36]
#define SM_BV    (SM_ZQST + 32*36)            // 52640
#define SM_BI    (SM_BV + NWARP*32)           // 53152
#define SM_FLOATS (SM_BI + NWARP*32)          // 53664
#define SMEM_BYTES (SM_FLOATS * 4)            // 214656 bytes

__device__ float g_cbn_v12[NQ*KC*CD];
__device__ float g_losspart_v12[NQ*NTILES];
__device__ int   g_tick_v12;

__device__ __forceinline__ void grid_barrier(int tid) {
    __syncthreads();
    if (tid == 0) {
        __threadfence();
        int t = atomicAdd(&g_tick_v12, 1);
        int target = (t / NCTA + 1) * NCTA;
        while (*(volatile int*)&g_tick_v12 < target) { }
        __threadfence();
    }
    __syncthreads();
}

__device__ __forceinline__ unsigned f2ord(float f) {
    int b = __float_as_int(f);
    return (b >= 0) ? ((unsigned)b | 0x80000000u) : ~(unsigned)b;
}

__device__ __forceinline__ void cp_async16(unsigned s, const void* g) {
    asm volatile("cp.async.cg.shared.global [%0], [%1], 16;" :: "r"(s), "l"(g));
}
#define CP_COMMIT() asm volatile("cp.async.commit_group;")
#define CP_WAIT0()  asm volatile("cp.async.wait_group 0;")

// 16-term ascending-c fma segment, CONTINUES accumulator sv.
// Two back-to-back segments on the same sv == v10's 32-term chain, bitwise.
#define CHAIN16(sv, A0,A1,A2,A3, E0,E1,E2,E3) \
    sv = fmaf(A0.x,E0.x,sv); sv = fmaf(A0.y,E0.y,sv); \
    sv = fmaf(A0.z,E0.z,sv); sv = fmaf(A0.w,E0.w,sv); \
    sv = fmaf(A1.x,E1.x,sv); sv = fmaf(A1.y,E1.y,sv); \
    sv = fmaf(A1.z,E1.z,sv); sv = fmaf(A1.w,E1.w,sv); \
    sv = fmaf(A2.x,E2.x,sv); sv = fmaf(A2.y,E2.y,sv); \
    sv = fmaf(A2.z,E2.z,sv); sv = fmaf(A2.w,E2.w,sv); \
    sv = fmaf(A3.x,E3.x,sv); sv = fmaf(A3.y,E3.y,sv); \
    sv = fmaf(A3.z,E3.z,sv); sv = fmaf(A3.w,E3.w,sv);

// ---------------- Single persistent kernel ----------------
__global__ __launch_bounds__(NTHR, 1)
void rvq_persist_v12(const float* __restrict__ x,
                     const float* __restrict__ in_w,
                     const float* __restrict__ in_b,
                     const float* __restrict__ out_w,
                     const float* __restrict__ out_b,
                     const float* __restrict__ cb,
                     float* __restrict__ out)
{
    extern __shared__ float sm[];
    float* RT   = sm + SM_RT;
    float* W0   = sm + SM_W;
    float* W1   = sm + SM_W + CD*256;
    float* ZE   = sm + SM_ZE;
    float* ENCT = sm + SM_ENCT;
    float* ZQST = sm + SM_ZQST;
    float* BV   = sm + SM_BV;
    int*   BI   = (int*)(sm + SM_BI);

    const int tid  = threadIdx.x;
    const int lane = tid & 31;
    const int wg   = tid >> 5;               // 0..15
    const int bid  = blockIdx.x;

    // ===== Prologue: normalize codebook rows (jnp rounding mimicry) =====
    {
        int gid = bid * NTHR + tid;
        if (gid < NQ*KC) {
            const float* src = cb + (size_t)gid * CD;
            float v[CD];
            float ss = 0.f;
#pragma unroll
            for (int c = 0; c < CD; c++) {
                v[c] = src[c];
                float vv = v[c] * v[c];
                ss = ss + vv;
            }
            float n = fmaxf(sqrtf(ss), 1e-12f);
            float* dst = g_cbn_v12 + (size_t)gid * CD;
#pragma unroll
            for (int c = 0; c < CD; c++) dst[c] = v[c] / n;
            __threadfence();
        }
    }
    grid_barrier(tid);

    // ===== Tile loop =====
    for (int blk = bid; blk < NTILES; blk += NCTA) {
        const int b  = blk >> 7;
        const int t0 = (blk & 127) << 5;
        const float* xg = x + (size_t)b * DDIM * TT + t0;

        for (int i = tid; i < DDIM*TILE; i += NTHR) {
            int d = i >> 5, t = i & 31;
            RT[t*RTP + d] = xg[(size_t)d * TT + t];
        }
        __syncthreads();

        for (int q = 0; q < NQ; q++) {
            const float* inw_q = in_w + (size_t)q * CD * DDIM;

            // pre-stage W chunk 0 via cp.async (all threads)
            {
                unsigned wb = (unsigned)__cvta_generic_to_shared(W0);
                for (int j = tid; j < CD*64; j += NTHR) {
                    int c = j >> 6, dq = j & 63;
                    cp_async16(wb + j*16, inw_q + (size_t)c*DDIM + dq*4);
                }
                CP_COMMIT();
            }

            // ===== Phase A: z_e = in_w @ R (8 warps x 4 ch; v5/v7/v10-bitwise) =====
            const int c0 = (wg & 7) * 4;
            float acc0 = 0.f, acc1 = 0.f, acc2 = 0.f, acc3 = 0.f;

            for (int ci = 0; ci < 4; ci++) {
                CP_WAIT0();
                __syncthreads();
                if (ci < 3) {
                    float* Wn = ((ci+1) & 1) ? W1 : W0;
                    unsigned wb = (unsigned)__cvta_generic_to_shared(Wn);
                    const int dcn = (ci+1) * 256;
                    for (int j = tid; j < CD*64; j += NTHR) {
                        int c = j >> 6, dq = j & 63;
                        cp_async16(wb + j*16, inw_q + (size_t)c*DDIM + dcn + dq*4);
                    }
                    CP_COMMIT();
                }
                if (wg < 8) {
                    const int dc = ci * 256;
                    const float* Wb  = (ci & 1) ? W1 : W0;
                    const float* Wr0 = Wb + (c0+0)*256;
                    const float* Wr1 = Wb + (c0+1)*256;
                    const float* Wr2 = Wb + (c0+2)*256;
                    const float* Wr3 = Wb + (c0+3)*256;
                    const float* Rrow = RT + lane*RTP + dc;
#pragma unroll 4
                    for (int dd = 0; dd < 256; dd += 4) {
                        float4 rv = *(const float4*)(Rrow + dd);
                        float4 w0 = *(const float4*)(Wr0 + dd);
                        float4 w1 = *(const float4*)(Wr1 + dd);
                        float4 w2 = *(const float4*)(Wr2 + dd);
                        float4 w3 = *(const float4*)(Wr3 + dd);
                        acc0 = fmaf(w0.x, rv.x, acc0); acc0 = fmaf(w0.y, rv.y, acc0);
                        acc0 = fmaf(w0.z, rv.z, acc0); acc0 = fmaf(w0.w, rv.w, acc0);
                        acc1 = fmaf(w1.x, rv.x, acc1); acc1 = fmaf(w1.y, rv.y, acc1);
                        acc1 = fmaf(w1.z, rv.z, acc1); acc1 = fmaf(w1.w, rv.w, acc1);
                        acc2 = fmaf(w2.x, rv.x, acc2); acc2 = fmaf(w2.y, rv.y, acc2);
                        acc2 = fmaf(w2.z, rv.z, acc2); acc2 = fmaf(w2.w, rv.w, acc2);
                        acc3 = fmaf(w3.x, rv.x, acc3); acc3 = fmaf(w3.y, rv.y, acc3);
                        acc3 = fmaf(w3.z, rv.z, acc3); acc3 = fmaf(w3.w, rv.w, acc3);
                    }
                }
                if (ci < 3) __syncthreads();
            }
            if (wg < 8) {
                const float* inb_q = in_b + q*CD;
                ZE[(c0+0)*33 + lane] = acc0 + __ldg(inb_q + c0 + 0);
                ZE[(c0+1)*33 + lane] = acc1 + __ldg(inb_q + c0 + 1);
                ZE[(c0+2)*33 + lane] = acc2 + __ldg(inb_q + c0 + 2);
                ZE[(c0+3)*33 + lane] = acc3 + __ldg(inb_q + c0 + 3);
            }
            __syncthreads();

            // prefetch both cbn rows (hidden behind warp0's enc)
            const float* cbn_q = g_cbn_v12 + (size_t)q * KC * CD;
            const float4* rp0 = (const float4*)(cbn_q + (size_t)(wg*64 + lane) * CD);
            const float4* rp1 = (const float4*)(cbn_q + (size_t)(wg*64 + 32 + lane) * CD);
            float4 ra0 = __ldg(rp0+0), ra1 = __ldg(rp0+1), ra2 = __ldg(rp0+2), ra3 = __ldg(rp0+3);
            float4 ra4 = __ldg(rp0+4), ra5 = __ldg(rp0+5), ra6 = __ldg(rp0+6), ra7 = __ldg(rp0+7);
            float4 rb0 = __ldg(rp1+0), rb1 = __ldg(rp1+1), rb2 = __ldg(rp1+2), rb3 = __ldg(rp1+3);
            float4 rb4 = __ldg(rp1+4), rb5 = __ldg(rp1+5), rb6 = __ldg(rp1+6), rb7 = __ldg(rp1+7);

            // ===== enc (bitwise = v6/v9/v10), transposed store =====
            if (wg == 0) {
                float n2 = 0.f;
#pragma unroll
                for (int c = 0; c < CD; c++) {
                    float z = ZE[c*33 + lane];
                    float zz = z * z;
                    n2 = n2 + zz;
                }
                float n = fmaxf(sqrtf(n2), 1e-12f);
#pragma unroll
                for (int c = 0; c < CD; c++)
                    ENCT[lane*36 + c] = ZE[c*33 + lane] / n;
            }
            __syncthreads();

            // ===== Phase B: 2 columns/iter, half-vector staging (4 chains ILP) =====
            {
                float bestv = 0.f; int bestk = 0;
                for (int t = 0; t < TILE; t += 2) {
                    const float4* evA = (const float4*)(ENCT + t*36);
                    const float4* evB = (const float4*)(ENCT + (t+1)*36);
                    float4 eA0 = evA[0], eA1 = evA[1], eA2 = evA[2], eA3 = evA[3];
                    float4 eB0 = evB[0], eB1 = evB[1], eB2 = evB[2], eB3 = evB[3];
                    float s0t = 0.f, s1t = 0.f, s0u = 0.f, s1u = 0.f;
                    CHAIN16(s0t, ra0,ra1,ra2,ra3, eA0,eA1,eA2,eA3);
                    CHAIN16(s1t, rb0,rb1,rb2,rb3, eA0,eA1,eA2,eA3);
                    CHAIN16(s0u, ra0,ra1,ra2,ra3, eB0,eB1,eB2,eB3);
                    CHAIN16(s1u, rb0,rb1,rb2,rb3, eB0,eB1,eB2,eB3);
                    eA0 = evA[4]; eA1 = evA[5]; eA2 = evA[6]; eA3 = evA[7];
                    eB0 = evB[4]; eB1 = evB[5]; eB2 = evB[6]; eB3 = evB[7];
                    CHAIN16(s0t, ra4,ra5,ra6,ra7, eA0,eA1,eA2,eA3);
                    CHAIN16(s1t, rb4,rb5,rb6,rb7, eA0,eA1,eA2,eA3);
                    CHAIN16(s0u, ra4,ra5,ra6,ra7, eB0,eB1,eB2,eB3);
                    CHAIN16(s1u, rb4,rb5,rb6,rb7, eB0,eB1,eB2,eB3);
                    // ---- argmax tails (semantics = v10: batch0 then batch1, strict >) ----
                    {   // column t
                        unsigned u0 = f2ord(s0t);
                        unsigned m0 = __reduce_max_sync(0xffffffffu, u0);
                        unsigned q0 = __ballot_sync(0xffffffffu, u0 == m0);
                        int l0 = __ffs(q0) - 1;
                        float sb0 = __shfl_sync(0xffffffffu, s0t, l0);
                        int   kb0 = wg*64 + l0;
                        unsigned u1 = f2ord(s1t);
                        unsigned m1 = __reduce_max_sync(0xffffffffu, u1);
                        unsigned q1 = __ballot_sync(0xffffffffu, u1 == m1);
                        int l1 = __ffs(q1) - 1;
                        float sb1 = __shfl_sync(0xffffffffu, s1t, l1);
                        int   kb1 = wg*64 + 32 + l1;
                        float bv = sb0; int bk = kb0;
                        if (sb1 > bv) { bv = sb1; bk = kb1; }
                        if (lane == t) { bestv = bv; bestk = bk; }
                    }
                    {   // column t+1
                        unsigned u0 = f2ord(s0u);
                        unsigned m0 = __reduce_max_sync(0xffffffffu, u0);
                        unsigned q0 = __ballot_sync(0xffffffffu, u0 == m0);
                        int l0 = __ffs(q0) - 1;
                        float sb0 = __shfl_sync(0xffffffffu, s0u, l0);
                        int   kb0 = wg*64 + l0;
                        unsigned u1 = f2ord(s1u);
                        unsigned m1 = __reduce_max_sync(0xffffffffu, u1);
                        unsigned q1 = __ballot_sync(0xffffffffu, u1 == m1);
                        int l1 = __ffs(q1) - 1;
                        float sb1 = __shfl_sync(0xffffffffu, s1u, l1);
                        int   kb1 = wg*64 + 32 + l1;
                        float bv = sb0; int bk = kb0;
                        if (sb1 > bv) { bv = sb1; bk = kb1; }
                        if (lane == t+1) { bestv = bv; bestk = bk; }
                    }
                }
                BV[wg*32 + lane] = bestv;
                BI[wg*32 + lane] = bestk;
            }
            __syncthreads();

            // prefetch out_w rows NOW (overlaps warp0's merge below)
            const float* outw_q = out_w + (size_t)q * DDIM * CD;
            const float* outb_q = out_b + (size_t)q * DDIM;
            const int d0 = wg*64 + lane, d1 = d0 + 32;
            const float4* wp0 = (const float4*)(outw_q + (size_t)d0 * CD);
            const float4* wp1 = (const float4*)(outw_q + (size_t)d1 * CD);
            float4 wa0 = __ldg(wp0+0), wa1 = __ldg(wp0+1), wa2 = __ldg(wp0+2), wa3 = __ldg(wp0+3);
            float4 wa4 = __ldg(wp0+4), wa5 = __ldg(wp0+5), wa6 = __ldg(wp0+6), wa7 = __ldg(wp0+7);
            float4 wb0 = __ldg(wp1+0), wb1 = __ldg(wp1+1), wb2 = __ldg(wp1+2), wb3 = __ldg(wp1+3);
            float4 wb4 = __ldg(wp1+4), wb5 = __ldg(wp1+5), wb6 = __ldg(wp1+6), wb7 = __ldg(wp1+7);
            float ob0 = __ldg(outb_q + d0), ob1 = __ldg(outb_q + d1);

            // cross-warp merge (ascending code ranges; strict >)
            if (wg == 0) {
                float fb = BV[lane]; int fi = BI[lane];
#pragma unroll
                for (int w2 = 1; w2 < NWARP; w2++) {
                    float v = BV[w2*32 + lane];
                    if (v > fb) { fb = v; fi = BI[w2*32 + lane]; }
                }
                BI[lane] = fi;
                out[QOFF + ((size_t)q * BB + b) * TT + t0 + lane] = (float)fi;
            }
            __syncthreads();

            // loss partial + STE build, z_q gathered directly from gmem
            {
                const float* cb_q = cb + (size_t)q * KC * CD;
                float lp = 0.f;
                for (int i = tid; i < CD*TILE; i += NTHR) {
                    int c = i >> 5, t = i & 31;
                    float ze = ZE[c*33 + t];
                    float zq = __ldg(cb_q + (size_t)BI[t] * CD + c);
                    float dv = ze - zq;
                    lp = fmaf(dv, dv, lp);
                    float dlt = zq - ze;          // STE: fl(z_e + fl(z_q - z_e))
                    ZQST[t*36 + c] = ze + dlt;
                }
#pragma unroll
                for (int o = 16; o; o >>= 1) lp += __shfl_down_sync(0xffffffffu, lp, o);
                if (lane == 0) BV[wg] = lp;
            }
            __syncthreads();
            if (tid == 0) {
                float s = 0.f;
#pragma unroll
                for (int w2 = 0; w2 < NWARP; w2++) s += BV[w2];
                g_losspart_v12[q*NTILES + blk] = s;
            }

            // ===== Phase C: 2 columns/iter, half-vector staging (values = v10) =====
            {
                for (int t = 0; t < TILE; t += 2) {
                    const float4* zvA = (const float4*)(ZQST + t*36);
                    const float4* zvB = (const float4*)(ZQST + (t+1)*36);
                    float4 zA0 = zvA[0], zA1 = zvA[1], zA2 = zvA[2], zA3 = zvA[3];
                    float4 zB0 = zvB[0], zB1 = zvB[1], zB2 = zvB[2], zB3 = zvB[3];
                    float v0t = 0.f, v1t = 0.f, v0u = 0.f, v1u = 0.f;
                    CHAIN16(v0t, wa0,wa1,wa2,wa3, zA0,zA1,zA2,zA3);
                    CHAIN16(v1t, wb0,wb1,wb2,wb3, zA0,zA1,zA2,zA3);
                    CHAIN16(v0u, wa0,wa1,wa2,wa3, zB0,zB1,zB2,zB3);
                    CHAIN16(v1u, wb0,wb1,wb2,wb3, zB0,zB1,zB2,zB3);
                    zA0 = zvA[4]; zA1 = zvA[5]; zA2 = zvA[6]; zA3 = zvA[7];
                    zB0 = zvB[4]; zB1 = zvB[5]; zB2 = zvB[6]; zB3 = zvB[7];
                    CHAIN16(v0t, wa4,wa5,wa6,wa7, zA0,zA1,zA2,zA3);
                    CHAIN16(v1t, wb4,wb5,wb6,wb7, zA0,zA1,zA2,zA3);
                    CHAIN16(v0u, wa4,wa5,wa6,wa7, zB0,zB1,zB2,zB3);
                    CHAIN16(v1u, wb4,wb5,wb6,wb7, zB0,zB1,zB2,zB3);
                    float o0t = v0t + ob0;        // bias after contraction
                    float o1t = v1t + ob1;
                    float o0u = v0u + ob0;
                    float o1u = v1u + ob1;
                    RT[t*RTP + d0]     = RT[t*RTP + d0]     - o0t;
                    RT[t*RTP + d1]     = RT[t*RTP + d1]     - o1t;
                    RT[(t+1)*RTP + d0] = RT[(t+1)*RTP + d0] - o0u;
                    RT[(t+1)*RTP + d1] = RT[(t+1)*RTP + d1] - o1u;
                }
            }
            __syncthreads();
        }

        // quantized_out = x - residual_final
        float* qo = out + (size_t)b * DDIM * TT + t0;
        for (int i = tid; i < DDIM*TILE; i += NTHR) {
            int d = i >> 5, t = i & 31;
            qo[(size_t)d * TT + t] = xg[(size_t)d * TT + t] - RT[t*RTP + d];
        }
        __syncthreads();
    }

    // ===== Epilogue: deterministic loss reduction (CTAs 0..7) =====
    if (tid == 0) __threadfence();
    grid_barrier(tid);
    if (bid < NQ) {
        float* red = sm;
        int q = bid;
        float s = 0.f;
        for (int i = tid; i < NTILES; i += NTHR) s += g_losspart_v12[q*NTILES + i];
        red[tid] = s;
        __syncthreads();
        for (int o = NTHR/2; o; o >>= 1) {
            if (tid < o) red[tid] += red[tid + o];
            __syncthreads();
        }
        if (tid == 0)
            out[IOFF + q] = 1.25f * red[0] * (1.0f / (float)(BB*CD*TT));
    }
}

// ---------------- launch ----------------
extern "C" void kernel_launch(void* const* d_in, const int* in_sizes, int n_in,
                              void* d_out, int out_size) {
    const float* x     = (const float*)d_in[0];
    const float* in_w  = (const float*)d_in[1];
    const float* in_b  = (const float*)d_in[2];
    const float* out_w = (const float*)d_in[3];
    const float* out_b = (const float*)d_in[4];
    const float* cb    = (const float*)d_in[5];
    float* out = (float*)d_out;

    cudaFuncSetAttribute(rvq_persist_v12, cudaFuncAttributeMaxDynamicSharedMemorySize, SMEM_BYTES);
    rvq_persist_v12<<<NCTA, NTHR, SMEM_BYTES>>>(x, in_w, in_b, out_w, out_b, cb, out);
}